// round 6
// baseline (speedup 1.0000x reference)
#include <cuda_runtime.h>

#define W_IMG 1024
#define H_IMG 1024
#define C_IMG 3
#define PLANE (H_IMG * W_IMG)

#define RPT 8                 // rows per thread
#define WARPS 8               // 256 threads -> tile 32 wide x 64 tall
#define BLOCK (32 * WARPS)

__global__ __launch_bounds__(BLOCK, 8) void homography_warp_kernel(
    const float* __restrict__ img,    // [N, C, H, W]
    const float* __restrict__ homo,   // [N, 3, 3]
    float* __restrict__ out)          // [N, C, H, W]
{
    const int n    = blockIdx.z;
    const int lane = threadIdx.x & 31;
    const int wrp  = threadIdx.x >> 5;
    const int w    = blockIdx.x * 32 + lane;
    const int h0   = (blockIdx.y * WARPS + wrp) * RPT;

    __shared__ float Hs[9];
    if (threadIdx.x < 9) Hs[threadIdx.x] = homo[n * 9 + threadIdx.x];
    __syncthreads();

    const float gx  = (float)w  * (2.0f / 1023.0f) - 1.0f;
    const float gy0 = (float)h0 * (2.0f / 1023.0f) - 1.0f;
    const float dg  = 2.0f / 1023.0f;

    // Transform at row h0; per-row increment = second column of H * dg.
    float Xr = Hs[0] * gx + Hs[1] * gy0 + Hs[2];
    float Yr = Hs[3] * gx + Hs[4] * gy0 + Hs[5];
    float Zr = Hs[6] * gx + Hs[7] * gy0 + Hs[8];
    const float dX = Hs[1] * dg;
    const float dY = Hs[4] * dg;
    const float dZ = Hs[7] * dg;

    // Channel-1-anchored bases: channel offsets +-PLANE (4MB) fit LDG/STG immediates.
    const float* pc1 = img + n * (C_IMG * PLANE) + PLANE;
    float*       oc1 = out + n * (C_IMG * PLANE) + PLANE + h0 * W_IMG + w;

    // Carried top-tap pair per channel (vertical reuse across rows).
    float t0c[3], t1c[3];
    bool  fastprev = false;
    int   offp = 0;

#pragma unroll
    for (int i = 0; i < RPT; i++) {
        const float inv = __fdividef(1.0f, Zr);
        const float x = fmaf(Xr * inv, 0.5f * (float)(W_IMG - 1), 0.5f * (float)(W_IMG - 1));
        const float y = fmaf(Yr * inv, 0.5f * (float)(H_IMG - 1), 0.5f * (float)(H_IMG - 1));
        Xr += dX; Yr += dY; Zr += dZ;

        const float x0f = floorf(x);
        const float y0f = floorf(y);
        const int x0 = (int)x0f;
        const int y0 = (int)y0f;
        const float fx = x - x0f;
        const float fy = y - y0f;
        const int off = y0 * W_IMG + x0;

        const bool interior = (x0 >= 0) & (x0 <= W_IMG - 2) & (y0 >= 0) & (y0 <= H_IMG - 2);

        if (__all_sync(0xFFFFFFFFu, interior)) {
            // ---- fast row: reuse previous row's bottom taps when the chain holds ----
            const bool reload = (i == 0) || !fastprev || (off != offp + W_IMG);
            const float* p = pc1 + off;

#pragma unroll
            for (int c = 0; c < C_IMG; c++) {
                const float* q = p + (c - 1) * PLANE;
                if (reload) {                       // predicated tap reload
                    t0c[c] = q[0];
                    t1c[c] = q[1];
                }
                const float b0 = q[W_IMG];
                const float b1 = q[W_IMG + 1];
                const float vt = fmaf(fx, t1c[c] - t0c[c], t0c[c]);
                const float vb = fmaf(fx, b1 - b0, b0);
                oc1[(c - 1) * PLANE + i * W_IMG] = fmaf(fy, vb - vt, vt);
                t0c[c] = b0; t1c[c] = b1;           // carry for next row
            }
            fastprev = true;
        } else {
            // ---- slow row (boundary warps): full masked/clamped zeros-padding ----
            const int xb = x0 + 1;
            const int yb = y0 + 1;

            const bool vx0 = (x0 >= 0) & (x0 < W_IMG);
            const bool vx1 = (xb >= 0) & (xb < W_IMG);
            const bool vy0 = (y0 >= 0) & (y0 < H_IMG);
            const bool vy1 = (yb >= 0) & (yb < H_IMG);

            const int x0c = min(max(x0, 0), W_IMG - 1);
            const int x1c = min(max(xb, 0), W_IMG - 1);
            const int y0c = min(max(y0, 0), H_IMG - 1);
            const int y1c = min(max(yb, 0), H_IMG - 1);

            const float wx0 = 1.0f - fx;
            const float wy0 = 1.0f - fy;

            const float w00 = (vx0 && vy0) ? (wx0 * wy0) : 0.0f;
            const float w01 = (vx1 && vy0) ? (fx  * wy0) : 0.0f;
            const float w10 = (vx0 && vy1) ? (wx0 * fy ) : 0.0f;
            const float w11 = (vx1 && vy1) ? (fx  * fy ) : 0.0f;

            const int r0 = y0c * W_IMG;
            const int r1 = y1c * W_IMG;

#pragma unroll
            for (int c = 0; c < C_IMG; c++) {
                const int co = (c - 1) * PLANE;
                const float v = pc1[co + r0 + x0c] * w00
                              + pc1[co + r0 + x1c] * w01
                              + pc1[co + r1 + x0c] * w10
                              + pc1[co + r1 + x1c] * w11;
                oc1[co + i * W_IMG] = v;
            }
            fastprev = false;
        }
        offp = off;
    }
}

extern "C" void kernel_launch(void* const* d_in, const int* in_sizes, int n_in,
                              void* d_out, int out_size) {
    const float* patch_src    = (const float*)d_in[0];  // [16,3,1024,1024]
    const float* dst_homo_src = (const float*)d_in[1];  // [16,3,3]
    float* out = (float*)d_out;

    dim3 grid(W_IMG / 32, H_IMG / (WARPS * RPT), 16);
    homography_warp_kernel<<<grid, BLOCK>>>(patch_src, dst_homo_src, out);
}